// round 4
// baseline (speedup 1.0000x reference)
#include <cuda_runtime.h>

#define BB   1024
#define CC   3
#define PROW 4
#define PCOL 5
#define PP   20      // PROW*PCOL
#define HID  32
#define HH   224
#define WW   220
#define PH   56      // HH/PROW
#define PW   44      // WW/PCOL
#define W4   55      // WW/4 float4 per row
#define PW4  11      // PW/4 float4 per column-patch
#define TY   4       // row-slots per block

// ---------------------------------------------------------------------------
// Fused kernel: grid = BB, block = (56, 4) = 224 threads. One block per image.
// 7 warps/block -> 9 blocks/SM resident -> all 1024 blocks fit in ONE wave
// (1332 slots), eliminating the 1.73-wave tail of the 448-thread version.
// Thread (tx, ty): tx = float4 column (tx<55 active), ty = row slot; loops
// over 3 channels x 4 row-patches x 14 row-groups, fully coalesced float4
// streaming loads (__ldcs), every 128B line fully consumed.
// ---------------------------------------------------------------------------
__global__ __launch_bounds__(56 * TY)
void nam_fused_kernel(const float* __restrict__ x,
                      const float* __restrict__ w1,
                      const float* __restrict__ b1,
                      const float* __restrict__ w2,
                      const float* __restrict__ b2,
                      float* __restrict__ out)
{
    const int b  = blockIdx.x;
    const int tx = threadIdx.x;   // 0..55
    const int ty = threadIdx.y;   // 0..3

    const float4* base = (const float4*)(x) + (size_t)b * (CC * HH * W4);

    float acc[PROW] = {0.f, 0.f, 0.f, 0.f};

    if (tx < W4) {
        #pragma unroll
        for (int c = 0; c < CC; c++) {
            const float4* cb = base + c * (HH * W4);
            #pragma unroll
            for (int pr = 0; pr < PROW; pr++) {
                #pragma unroll
                for (int i = 0; i < PH / TY; i++) {     // 14 row-groups
                    const int h = pr * PH + i * TY + ty;
                    float4 v = __ldcs(&cb[h * W4 + tx]);
                    acc[pr] += (v.x + v.y) + (v.z + v.w);
                }
            }
        }
    }

    __shared__ float part[PROW][TY][56];
    #pragma unroll
    for (int pr = 0; pr < PROW; pr++)
        part[pr][ty][tx] = acc[pr];                      // tx==55 stores 0
    __syncthreads();

    // Warp 0, lanes 0..19: patch p = pr*5 + pc. Reduce TY x 11 partials, MLP.
    const int tid = ty * 56 + tx;
    if (tid < 32) {
        float o = 0.f;
        if (tid < PP) {
            const int pr = tid / PCOL;
            const int pc = tid % PCOL;
            float s = 0.f;
            #pragma unroll
            for (int yy = 0; yy < TY; yy++) {
                float a = 0.f;
                #pragma unroll
                for (int k = 0; k < PW4; k++)
                    a += part[pr][yy][pc * PW4 + k];
                s += a;
            }
            const float f = s * (1.0f / (CC * PH * PW)); // mean over 7392 elems

            o = b2[tid];
            const float* w1p = w1 + tid * HID;
            const float* b1p = b1 + tid * HID;
            const float* w2p = w2 + tid * HID;
            #pragma unroll
            for (int k = 0; k < HID; k++) {
                float h = fmaf(f, w1p[k], b1p[k]);
                h = fmaxf(h, 0.0f);
                o = fmaf(h, w2p[k], o);
            }
            out[BB + b * PP + tid] = o;                  // contribs section
        }
        // score = sum of 20 contribs (lanes >= 20 contribute 0)
        float sc = o;
        #pragma unroll
        for (int off = 16; off > 0; off >>= 1)
            sc += __shfl_down_sync(0xFFFFFFFFu, sc, off);
        if (tid == 0)
            out[b] = sc;                                 // score section
    }
}

extern "C" void kernel_launch(void* const* d_in, const int* in_sizes, int n_in,
                              void* d_out, int out_size)
{
    const float* x  = (const float*)d_in[0];
    const float* w1 = (const float*)d_in[1];
    const float* b1 = (const float*)d_in[2];
    const float* w2 = (const float*)d_in[3];
    const float* b2 = (const float*)d_in[4];
    float* out = (float*)d_out;

    nam_fused_kernel<<<BB, dim3(56, TY)>>>(x, w1, b1, w2, b2, out);
}

// round 5
// speedup vs baseline: 1.1495x; 1.1495x over previous
#include <cuda_runtime.h>

#define BB   1024
#define CC   3
#define PROW 4
#define PCOL 5
#define PP   20      // PROW*PCOL
#define HID  32
#define HH   224
#define WW   220
#define PH   56      // HH/PROW
#define PW   44      // WW/PCOL
#define W4   55      // WW/4 float4 per row
#define PW4  11      // PW/4 float4 per column-patch

// per-(image, patch, channel) partial sums + fan-in counters
__device__ float        g_sums[BB][PP][CC];
__device__ unsigned int g_cnt[BB];          // zero-init; atomicInc wraps back to 0

// ---------------------------------------------------------------------------
// Single fused kernel, fine-grained: grid = (BB, CC), block = (56, 8).
// Pool phase identical to the R2 kernel that measured 6.95 TB/s.
// The LAST block to finish an image (atomicInc fan-in, self-resetting for
// graph replay) runs the per-patch MLP + score on warp 0 — overlapped with
// other blocks' pooling, so the old 11us second kernel disappears.
// ---------------------------------------------------------------------------
__global__ __launch_bounds__(448)
void nam_fused_lastblock(const float* __restrict__ x,
                         const float* __restrict__ w1,
                         const float* __restrict__ b1,
                         const float* __restrict__ w2,
                         const float* __restrict__ b2,
                         float* __restrict__ out)
{
    const int b  = blockIdx.x;
    const int c  = blockIdx.y;
    const int tx = threadIdx.x;   // 0..55 (55 idle for loads)
    const int ty = threadIdx.y;   // 0..7

    const float4* base = (const float4*)(x) + (size_t)(b * CC + c) * (HH * W4);

    float acc[PROW] = {0.f, 0.f, 0.f, 0.f};

    if (tx < W4) {
        #pragma unroll
        for (int pr = 0; pr < PROW; pr++) {
            #pragma unroll
            for (int i = 0; i < PH / 8; i++) {          // 7 row-groups
                const int h = pr * PH + i * 8 + ty;
                float4 v = base[h * W4 + tx];
                acc[pr] += (v.x + v.y) + (v.z + v.w);
            }
        }
    }

    __shared__ float part[PROW][8][56];
    #pragma unroll
    for (int pr = 0; pr < PROW; pr++)
        part[pr][ty][tx] = acc[pr];                      // tx==55 stores 0
    __syncthreads();

    // 20 reducer threads: patch p = pr*5 + pc, write per-channel patch sum.
    const int tid = ty * 56 + tx;
    if (tid < PP) {
        const int pr = tid / PCOL;
        const int pc = tid % PCOL;
        float s = 0.f;
        #pragma unroll
        for (int yy = 0; yy < 8; yy++) {
            float a = 0.f;
            #pragma unroll
            for (int k = 0; k < PW4; k++)
                a += part[pr][yy][pc * PW4 + k];
            s += a;
        }
        g_sums[b][tid][c] = s;
    }
    __syncthreads();

    // Fan-in: last block for this image runs the MLP.
    __shared__ unsigned int s_last;
    if (tid == 0) {
        __threadfence();                                  // publish g_sums writes
        unsigned int old = atomicInc(&g_cnt[b], CC - 1);  // wraps to 0 -> replayable
        s_last = (old == CC - 1) ? 1u : 0u;
    }
    __syncthreads();

    if (s_last && tid < 32) {
        __threadfence();                                  // order after the atomic
        float o = 0.f;
        if (tid < PP) {
            // __ldcg: read from L2, bypass (possibly stale-empty) L1
            const float f = (__ldcg(&g_sums[b][tid][0]) +
                             __ldcg(&g_sums[b][tid][1]) +
                             __ldcg(&g_sums[b][tid][2])) * (1.0f / (CC * PH * PW));
            o = b2[tid];
            const float* w1p = w1 + tid * HID;
            const float* b1p = b1 + tid * HID;
            const float* w2p = w2 + tid * HID;
            #pragma unroll
            for (int k = 0; k < HID; k++) {
                float h = fmaf(f, w1p[k], b1p[k]);
                h = fmaxf(h, 0.0f);
                o = fmaf(h, w2p[k], o);
            }
            out[BB + b * PP + tid] = o;                   // contribs section
        }
        float sc = o;                                     // lanes >= 20 add 0
        #pragma unroll
        for (int off = 16; off > 0; off >>= 1)
            sc += __shfl_down_sync(0xFFFFFFFFu, sc, off);
        if (tid == 0)
            out[b] = sc;                                  // score section
    }
}

extern "C" void kernel_launch(void* const* d_in, const int* in_sizes, int n_in,
                              void* d_out, int out_size)
{
    const float* x  = (const float*)d_in[0];
    const float* w1 = (const float*)d_in[1];
    const float* b1 = (const float*)d_in[2];
    const float* w2 = (const float*)d_in[3];
    const float* b2 = (const float*)d_in[4];
    float* out = (float*)d_out;

    nam_fused_lastblock<<<dim3(BB, CC), dim3(56, 8)>>>(x, w1, b1, w2, b2, out);
}